// round 8
// baseline (speedup 1.0000x reference)
#include <cuda_runtime.h>
#include <cuda_bf16.h>

#define NB 16
#define NC 128
#define NHEADS 4
#define ND 32
#define NN 1024
#define NBH (NB * NHEADS)
#define FULLM 0xFFFFFFFFu

// Static device scratch (allocation-free).
// q, k': packed (hi,lo) bf16 in one u32, layout [bh][n][d]  (8 MB each)
// v: hi/lo bf16 planes, layout [bh][d][n] stored as u32 j-pairs (4 MB each)
__device__ __align__(16) unsigned g_qpk[NBH * NN * ND];
__device__ __align__(16) unsigned g_kpk[NBH * NN * ND];
__device__ __align__(16) unsigned g_vhi[NBH * ND * (NN / 2)];
__device__ __align__(16) unsigned g_vlo[NBH * ND * (NN / 2)];

// ---------------- bf16 helpers ----------------
__device__ __forceinline__ unsigned pk_split(float x) {
    __nv_bfloat16 h = __float2bfloat16(x);
    float hf = __bfloat162float(h);
    __nv_bfloat16 l = __float2bfloat16(x - hf);
    return (unsigned)__bfloat16_as_ushort(h) | ((unsigned)__bfloat16_as_ushort(l) << 16);
}
__device__ __forceinline__ unsigned pk_hi2(float a, float b) {
    return (unsigned)__bfloat16_as_ushort(__float2bfloat16(a)) |
           ((unsigned)__bfloat16_as_ushort(__float2bfloat16(b)) << 16);
}
// pack2(lo, hi): bf16x2 with lo in bits[0:16)
__device__ __forceinline__ unsigned pack2(float lo, float hi) {
    unsigned r;
    asm("cvt.rn.bf16x2.f32 %0, %1, %2;" : "=r"(r) : "f"(hi), "f"(lo));
    return r;
}

// m16n8k16 bf16 MMA, fp32 accumulate (sm_80+ baseline — legal on compute_103)
__device__ __forceinline__ void mma_bf16(float& c0, float& c1, float& c2, float& c3,
                                         unsigned a0, unsigned a1, unsigned a2, unsigned a3,
                                         unsigned b0, unsigned b1) {
    asm volatile(
        "mma.sync.aligned.m16n8k16.row.col.f32.bf16.bf16.f32 "
        "{%0,%1,%2,%3}, {%4,%5,%6,%7}, {%8,%9}, {%0,%1,%2,%3};"
        : "+f"(c0), "+f"(c1), "+f"(c2), "+f"(c3)
        : "r"(a0), "r"(a1), "r"(a2), "r"(a3), "r"(b0), "r"(b1));
}

// ---------------------------------------------------------------------------
// Kernel 1: QKV projection (fp32) + relative-position fold into K.
// Emits packed/split bf16 operand tensors for the MMA attention kernel.
// ---------------------------------------------------------------------------
__global__ __launch_bounds__(256) void qkv_kernel(
    const float* __restrict__ x, const float* __restrict__ Wq,
    const float* __restrict__ rw, const float* __restrict__ rh)
{
    __shared__ float Ws[64][33];
    __shared__ float xs[32][64];

    int t  = threadIdx.x;
    int n0 = blockIdx.x * 64;
    int o0 = blockIdx.y * 64;
    int b  = blockIdx.z;
    int ti = t >> 4, tj = t & 15;

    float4 acc[4];
#pragma unroll
    for (int k = 0; k < 4; k++) acc[k] = make_float4(0.f, 0.f, 0.f, 0.f);

    for (int kc = 0; kc < 128; kc += 32) {
        __syncthreads();
#pragma unroll
        for (int k = 0; k < 2; k++) {
            int f  = t * 2 + k;
            int oo = f >> 3, c4 = (f & 7) * 4;
            float4 w = *(const float4*)&Wq[(o0 + oo) * 128 + kc + c4];
            Ws[oo][c4 + 0] = w.x; Ws[oo][c4 + 1] = w.y;
            Ws[oo][c4 + 2] = w.z; Ws[oo][c4 + 3] = w.w;
            int cc = f >> 4, nb = (f & 15) * 4;
            *(float4*)&xs[cc][nb] =
                *(const float4*)&x[(size_t)b * NC * NN + (size_t)(kc + cc) * NN + n0 + nb];
        }
        __syncthreads();
#pragma unroll
        for (int cc = 0; cc < 32; ++cc) {
            float4 xv = *(const float4*)&xs[cc][tj * 4];
            float q0 = Ws[ti * 4 + 0][cc];
            float q1 = Ws[ti * 4 + 1][cc];
            float q2 = Ws[ti * 4 + 2][cc];
            float q3 = Ws[ti * 4 + 3][cc];
            acc[0].x = fmaf(q0, xv.x, acc[0].x); acc[0].y = fmaf(q0, xv.y, acc[0].y);
            acc[0].z = fmaf(q0, xv.z, acc[0].z); acc[0].w = fmaf(q0, xv.w, acc[0].w);
            acc[1].x = fmaf(q1, xv.x, acc[1].x); acc[1].y = fmaf(q1, xv.y, acc[1].y);
            acc[1].z = fmaf(q1, xv.z, acc[1].z); acc[1].w = fmaf(q1, xv.w, acc[1].w);
            acc[2].x = fmaf(q2, xv.x, acc[2].x); acc[2].y = fmaf(q2, xv.y, acc[2].y);
            acc[2].z = fmaf(q2, xv.z, acc[2].z); acc[2].w = fmaf(q2, xv.w, acc[2].w);
            acc[3].x = fmaf(q3, xv.x, acc[3].x); acc[3].y = fmaf(q3, xv.y, acc[3].y);
            acc[3].z = fmaf(q3, xv.z, acc[3].z); acc[3].w = fmaf(q3, xv.w, acc[3].w);
        }
    }

    const float scale = 0.17677669529663689f;  // 1/sqrt(32)
    int s  = o0 >> 7;              // 0=q, 1=k, 2=v
    int n  = n0 + tj * 4;
    int hh = n >> 5, w0 = n & 31;
#pragma unroll
    for (int k = 0; k < 4; k++) {
        int o  = o0 + ti * 4 + k;
        int oh = o & 127;
        int h  = oh >> 5, dd = oh & 31;
        int bh = b * NHEADS + h;
        float4 v = acc[k];
        if (s == 1) {          // fold relative position into K
            int rbase = (h * ND + dd) * 32;
            float rhv = rh[rbase + hh];
            v.x += rw[rbase + w0 + 0] + rhv;
            v.y += rw[rbase + w0 + 1] + rhv;
            v.z += rw[rbase + w0 + 2] + rhv;
            v.w += rw[rbase + w0 + 3] + rhv;
            size_t base = ((size_t)bh * NN + n) * ND + dd;
            g_kpk[base + 0 * ND] = pk_split(v.x);
            g_kpk[base + 1 * ND] = pk_split(v.y);
            g_kpk[base + 2 * ND] = pk_split(v.z);
            g_kpk[base + 3 * ND] = pk_split(v.w);
        } else if (s == 0) {   // pre-scale q
            v.x *= scale; v.y *= scale; v.z *= scale; v.w *= scale;
            size_t base = ((size_t)bh * NN + n) * ND + dd;
            g_qpk[base + 0 * ND] = pk_split(v.x);
            g_qpk[base + 1 * ND] = pk_split(v.y);
            g_qpk[base + 2 * ND] = pk_split(v.z);
            g_qpk[base + 3 * ND] = pk_split(v.w);
        } else {               // v: hi/lo planes, [d][n] as u32 j-pairs
            float xh = __bfloat162float(__float2bfloat16(v.x));
            float yh = __bfloat162float(__float2bfloat16(v.y));
            float zh = __bfloat162float(__float2bfloat16(v.z));
            float wh = __bfloat162float(__float2bfloat16(v.w));
            size_t base = ((size_t)bh * ND + dd) * (NN / 2) + (n >> 1);
            g_vhi[base + 0] = pk_hi2(v.x, v.y);
            g_vhi[base + 1] = pk_hi2(v.z, v.w);
            g_vlo[base + 0] = pk_hi2(v.x - xh, v.y - yh);
            g_vlo[base + 1] = pk_hi2(v.z - zh, v.w - wh);
        }
    }
}

// ---------------------------------------------------------------------------
// Kernel 2: flash attention via mma.sync bf16 (fp32-exact split, no-max softmax).
// CTA = 128 threads (4 warps), i-tile 128 (32 rows/warp), 16 j-tiles of 64.
// Changes vs r7: swap applied to B-frags (PRMT, no qsw array), GEMM2 fused
// per-kt2 (phi/plo 8+8 regs), smem pitch 36 (conflict-free frag loads),
// __launch_bounds__(128,3) for 3 CTAs/SM.
// ---------------------------------------------------------------------------
__global__ __launch_bounds__(128, 3) void attn_kernel(float* __restrict__ out)
{
    __shared__ unsigned ks[64][36];   // [j][d u32], pitch 36: bank=(4g+tq)%32 distinct
    __shared__ unsigned vh[32][36];   // [d][j-pair u32]
    __shared__ unsigned vl[32][36];

    int t    = threadIdx.x;
    int wid  = t >> 5, lane = t & 31;
    int g    = lane >> 2, tq = lane & 3;       // groupID, threadID-in-quad
    int bh   = blockIdx.x >> 3;
    int i0   = (blockIdx.x & 7) * 128;
    int ib   = wid * 32;

    const unsigned* gq  = g_qpk + (size_t)bh * NN * ND;
    const unsigned* gk  = g_kpk + (size_t)bh * NN * ND;
    const unsigned* gvh = g_vhi + (size_t)bh * ND * (NN / 2);
    const unsigned* gvl = g_vlo + (size_t)bh * ND * (NN / 2);

    // --- Q A-fragments (held all kernel): qa[mb*16 + kt*4 + {0..3}] ---
    unsigned qa[32];
#pragma unroll
    for (int mb = 0; mb < 2; mb++) {
        int rg  = i0 + ib + mb * 16 + g;
        int rg8 = rg + 8;
#pragma unroll
        for (int kt = 0; kt < 4; kt++) {
            int c0 = kt * 8 + tq, c4 = c0 + 4;
            unsigned* a = &qa[mb * 16 + kt * 4];
            a[0] = gq[rg  * ND + c0];
            a[1] = gq[rg8 * ND + c0];
            a[2] = gq[rg  * ND + c4];
            a[3] = gq[rg8 * ND + c4];
        }
    }

    float oacc[32];
#pragma unroll
    for (int i = 0; i < 32; i++) oacc[i] = 0.f;
    float lsum[4] = {0.f, 0.f, 0.f, 0.f};   // [mb][row g / g+8]

    for (int jt = 0; jt < 16; ++jt) {
        int j0 = jt * 64;
        __syncthreads();
        // ---- fill K tile (64x32 u32) and V hi/lo tiles (32x32 u32 each) ----
#pragma unroll
        for (int i = 0; i < 16; i++) {
            int idx = t + i * 128;
            ks[idx >> 5][idx & 31] = gk[(j0 + (idx >> 5)) * ND + (idx & 31)];
        }
#pragma unroll
        for (int i = 0; i < 8; i++) {
            int idx = t + i * 128;
            int r = idx >> 5, c = idx & 31;
            vh[r][c] = gvh[(size_t)r * (NN / 2) + (j0 >> 1) + c];
            vl[r][c] = gvl[(size_t)r * (NN / 2) + (j0 >> 1) + c];
        }
        __syncthreads();

        // ---- per 16-wide j-chunk: GEMM1 + exp + immediate GEMM2 ----
#pragma unroll
        for (int kt2 = 0; kt2 < 4; kt2++) {
            unsigned phi[2][4], plo[2][4];
#pragma unroll
            for (int half = 0; half < 2; half++) {
                int nb = kt2 * 2 + half;
                float c[8];
#pragma unroll
                for (int i = 0; i < 8; i++) c[i] = 0.f;
#pragma unroll
                for (int kt = 0; kt < 4; kt++) {
                    unsigned b0 = ks[nb * 8 + g][kt * 8 + tq];
                    unsigned b1 = ks[nb * 8 + g][kt * 8 + tq + 4];
                    unsigned s0 = __byte_perm(b0, 0, 0x1032);   // swap-on-B
                    unsigned s1 = __byte_perm(b1, 0, 0x1032);
#pragma unroll
                    for (int mb = 0; mb < 2; mb++) {
                        const unsigned* a = &qa[mb * 16 + kt * 4];
                        mma_bf16(c[mb*4], c[mb*4+1], c[mb*4+2], c[mb*4+3],
                                 a[0], a[1], a[2], a[3], b0, b1);
                        mma_bf16(c[mb*4], c[mb*4+1], c[mb*4+2], c[mb*4+3],
                                 a[0], a[1], a[2], a[3], s0, s1);
                    }
                }
                int off = half * 2;
#pragma unroll
                for (int mb = 0; mb < 2; mb++) {
                    float p0 = __expf(c[mb*4+0]);
                    float p1 = __expf(c[mb*4+1]);
                    float p2 = __expf(c[mb*4+2]);
                    float p3 = __expf(c[mb*4+3]);
                    lsum[mb*2+0] += p0 + p1;
                    lsum[mb*2+1] += p2 + p3;
                    unsigned hp01 = pack2(p0, p1);
                    unsigned hp23 = pack2(p2, p3);
                    float h0 = __uint_as_float(hp01 << 16);
                    float h1 = __uint_as_float(hp01 & 0xFFFF0000u);
                    float h2 = __uint_as_float(hp23 << 16);
                    float h3 = __uint_as_float(hp23 & 0xFFFF0000u);
                    phi[mb][off + 0] = hp01;                     // rows g   (a0/a2)
                    phi[mb][off + 1] = hp23;                     // rows g+8 (a1/a3)
                    plo[mb][off + 0] = pack2(p0 - h0, p1 - h1);
                    plo[mb][off + 1] = pack2(p2 - h2, p3 - h3);
                }
            }
            // ---- GEMM2 for this kt2: O += Phi·Vh + Phi·Vl + Plo·Vh ----
#pragma unroll
            for (int nb2 = 0; nb2 < 4; nb2++) {
                unsigned bh0 = vh[nb2 * 8 + g][kt2 * 8 + tq];
                unsigned bh1 = vh[nb2 * 8 + g][kt2 * 8 + tq + 4];
                unsigned bl0 = vl[nb2 * 8 + g][kt2 * 8 + tq];
                unsigned bl1 = vl[nb2 * 8 + g][kt2 * 8 + tq + 4];
#pragma unroll
                for (int mb = 0; mb < 2; mb++) {
                    float* o = &oacc[(mb * 4 + nb2) * 4];
                    const unsigned* ah = phi[mb];
                    const unsigned* al = plo[mb];
                    mma_bf16(o[0], o[1], o[2], o[3], ah[0], ah[1], ah[2], ah[3], bh0, bh1);
                    mma_bf16(o[0], o[1], o[2], o[3], ah[0], ah[1], ah[2], ah[3], bl0, bl1);
                    mma_bf16(o[0], o[1], o[2], o[3], al[0], al[1], al[2], al[3], bh0, bh1);
                }
            }
        }
    }

    // ---- finalize: quad-reduce row sums, divide, store ----
#pragma unroll
    for (int i = 0; i < 4; i++) {
        lsum[i] += __shfl_xor_sync(FULLM, lsum[i], 1);
        lsum[i] += __shfl_xor_sync(FULLM, lsum[i], 2);
    }
    int b = bh >> 2, h = bh & 3;
    size_t cbase = (size_t)b * NC + h * ND;
#pragma unroll
    for (int mb = 0; mb < 2; mb++) {
        int rg = i0 + ib + mb * 16 + g;
        float inv0 = 1.f / lsum[mb * 2 + 0];
        float inv1 = 1.f / lsum[mb * 2 + 1];
#pragma unroll
        for (int nb2 = 0; nb2 < 4; nb2++) {
            const float* o = &oacc[(mb * 4 + nb2) * 4];
            int d0 = nb2 * 8 + 2 * tq;
            out[(cbase + d0    ) * NN + rg    ] = o[0] * inv0;
            out[(cbase + d0 + 1) * NN + rg    ] = o[1] * inv0;
            out[(cbase + d0    ) * NN + rg + 8] = o[2] * inv1;
            out[(cbase + d0 + 1) * NN + rg + 8] = o[3] * inv1;
        }
    }
}

extern "C" void kernel_launch(void* const* d_in, const int* in_sizes, int n_in,
                              void* d_out, int out_size)
{
    const float* x  = (const float*)d_in[0];
    const float* Wq = (const float*)d_in[1];
    const float* rw = (const float*)d_in[2];
    const float* rh = (const float*)d_in[3];
    float* out = (float*)d_out;

    dim3 g1(NN / 64, (3 * NC) / 64, NB);
    qkv_kernel<<<g1, 256>>>(x, Wq, rw, rh);

    attn_kernel<<<NBH * 8, 128>>>(out);   // 512 CTAs
}

// round 11
// speedup vs baseline: 1.1720x; 1.1720x over previous
#include <cuda_runtime.h>
#include <cuda_bf16.h>

#define NB 16
#define NC 128
#define NHEADS 4
#define ND 32
#define NN 1024
#define NBH (NB * NHEADS)
#define FULLM 0xFFFFFFFFu

// Static device scratch (allocation-free).
// q, k': packed (hi,lo) bf16 in one u32, layout [bh][n][d]  (8 MB each)
// v: hi/lo bf16 planes, layout [bh][d][n] stored as u32 j-pairs (4 MB each)
__device__ __align__(16) unsigned g_qpk[NBH * NN * ND];
__device__ __align__(16) unsigned g_kpk[NBH * NN * ND];
__device__ __align__(16) unsigned g_vhi[NBH * ND * (NN / 2)];
__device__ __align__(16) unsigned g_vlo[NBH * ND * (NN / 2)];

// ---------------- bf16 helpers ----------------
__device__ __forceinline__ unsigned pk_split(float x) {
    __nv_bfloat16 h = __float2bfloat16(x);
    float hf = __bfloat162float(h);
    __nv_bfloat16 l = __float2bfloat16(x - hf);
    return (unsigned)__bfloat16_as_ushort(h) | ((unsigned)__bfloat16_as_ushort(l) << 16);
}
__device__ __forceinline__ unsigned pk_hi2(float a, float b) {
    return (unsigned)__bfloat16_as_ushort(__float2bfloat16(a)) |
           ((unsigned)__bfloat16_as_ushort(__float2bfloat16(b)) << 16);
}
// pack2(lo, hi): bf16x2 with lo in bits[0:16)
__device__ __forceinline__ unsigned pack2(float lo, float hi) {
    unsigned r;
    asm("cvt.rn.bf16x2.f32 %0, %1, %2;" : "=r"(r) : "f"(hi), "f"(lo));
    return r;
}
__device__ __forceinline__ float ex2(float x) {
    float y;
    asm("ex2.approx.ftz.f32 %0, %1;" : "=f"(y) : "f"(x));
    return y;
}

// m16n8k16 bf16 MMA, fp32 accumulate (sm_80+ baseline — legal on compute_103)
__device__ __forceinline__ void mma_bf16(float& c0, float& c1, float& c2, float& c3,
                                         unsigned a0, unsigned a1, unsigned a2, unsigned a3,
                                         unsigned b0, unsigned b1) {
    asm volatile(
        "mma.sync.aligned.m16n8k16.row.col.f32.bf16.bf16.f32 "
        "{%0,%1,%2,%3}, {%4,%5,%6,%7}, {%8,%9}, {%0,%1,%2,%3};"
        : "+f"(c0), "+f"(c1), "+f"(c2), "+f"(c3)
        : "r"(a0), "r"(a1), "r"(a2), "r"(a3), "r"(b0), "r"(b1));
}

// ---------------- cp.async helpers (sm_80 baseline) ----------------
__device__ __forceinline__ void cpa16(void* dst, const void* src) {
    unsigned a = (unsigned)__cvta_generic_to_shared(dst);
    asm volatile("cp.async.cg.shared.global [%0], [%1], 16;" :: "r"(a), "l"(src));
}
#define CP_COMMIT() asm volatile("cp.async.commit_group;" ::: "memory")
#define CP_WAIT(n)  asm volatile("cp.async.wait_group %0;" :: "n"(n) : "memory")

// ---------------------------------------------------------------------------
// Kernel 1: QKV projection (fp32) + relative-position fold into K.
// q pre-scale now includes log2(e) so attn can use raw ex2.
// ---------------------------------------------------------------------------
__global__ __launch_bounds__(256) void qkv_kernel(
    const float* __restrict__ x, const float* __restrict__ Wq,
    const float* __restrict__ rw, const float* __restrict__ rh)
{
    __shared__ float Ws[64][33];
    __shared__ float xs[32][64];

    int t  = threadIdx.x;
    int n0 = blockIdx.x * 64;
    int o0 = blockIdx.y * 64;
    int b  = blockIdx.z;
    int ti = t >> 4, tj = t & 15;

    float4 acc[4];
#pragma unroll
    for (int k = 0; k < 4; k++) acc[k] = make_float4(0.f, 0.f, 0.f, 0.f);

    for (int kc = 0; kc < 128; kc += 32) {
        __syncthreads();
#pragma unroll
        for (int k = 0; k < 2; k++) {
            int f  = t * 2 + k;
            int oo = f >> 3, c4 = (f & 7) * 4;
            float4 w = *(const float4*)&Wq[(o0 + oo) * 128 + kc + c4];
            Ws[oo][c4 + 0] = w.x; Ws[oo][c4 + 1] = w.y;
            Ws[oo][c4 + 2] = w.z; Ws[oo][c4 + 3] = w.w;
            int cc = f >> 4, nb = (f & 15) * 4;
            *(float4*)&xs[cc][nb] =
                *(const float4*)&x[(size_t)b * NC * NN + (size_t)(kc + cc) * NN + n0 + nb];
        }
        __syncthreads();
#pragma unroll
        for (int cc = 0; cc < 32; ++cc) {
            float4 xv = *(const float4*)&xs[cc][tj * 4];
            float q0 = Ws[ti * 4 + 0][cc];
            float q1 = Ws[ti * 4 + 1][cc];
            float q2 = Ws[ti * 4 + 2][cc];
            float q3 = Ws[ti * 4 + 3][cc];
            acc[0].x = fmaf(q0, xv.x, acc[0].x); acc[0].y = fmaf(q0, xv.y, acc[0].y);
            acc[0].z = fmaf(q0, xv.z, acc[0].z); acc[0].w = fmaf(q0, xv.w, acc[0].w);
            acc[1].x = fmaf(q1, xv.x, acc[1].x); acc[1].y = fmaf(q1, xv.y, acc[1].y);
            acc[1].z = fmaf(q1, xv.z, acc[1].z); acc[1].w = fmaf(q1, xv.w, acc[1].w);
            acc[2].x = fmaf(q2, xv.x, acc[2].x); acc[2].y = fmaf(q2, xv.y, acc[2].y);
            acc[2].z = fmaf(q2, xv.z, acc[2].z); acc[2].w = fmaf(q2, xv.w, acc[2].w);
            acc[3].x = fmaf(q3, xv.x, acc[3].x); acc[3].y = fmaf(q3, xv.y, acc[3].y);
            acc[3].z = fmaf(q3, xv.z, acc[3].z); acc[3].w = fmaf(q3, xv.w, acc[3].w);
        }
    }

    // 1/sqrt(32) * log2(e): exp(S) == exp2(S'), S' built from pre-scaled q
    const float scale = 0.17677669529663689f * 1.4426950408889634f;
    int s  = o0 >> 7;              // 0=q, 1=k, 2=v
    int n  = n0 + tj * 4;
    int hh = n >> 5, w0 = n & 31;
#pragma unroll
    for (int k = 0; k < 4; k++) {
        int o  = o0 + ti * 4 + k;
        int oh = o & 127;
        int h  = oh >> 5, dd = oh & 31;
        int bh = b * NHEADS + h;
        float4 v = acc[k];
        if (s == 1) {          // fold relative position into K
            int rbase = (h * ND + dd) * 32;
            float rhv = rh[rbase + hh];
            v.x += rw[rbase + w0 + 0] + rhv;
            v.y += rw[rbase + w0 + 1] + rhv;
            v.z += rw[rbase + w0 + 2] + rhv;
            v.w += rw[rbase + w0 + 3] + rhv;
            size_t base = ((size_t)bh * NN + n) * ND + dd;
            g_kpk[base + 0 * ND] = pk_split(v.x);
            g_kpk[base + 1 * ND] = pk_split(v.y);
            g_kpk[base + 2 * ND] = pk_split(v.z);
            g_kpk[base + 3 * ND] = pk_split(v.w);
        } else if (s == 0) {   // pre-scale q (incl log2e)
            v.x *= scale; v.y *= scale; v.z *= scale; v.w *= scale;
            size_t base = ((size_t)bh * NN + n) * ND + dd;
            g_qpk[base + 0 * ND] = pk_split(v.x);
            g_qpk[base + 1 * ND] = pk_split(v.y);
            g_qpk[base + 2 * ND] = pk_split(v.z);
            g_qpk[base + 3 * ND] = pk_split(v.w);
        } else {               // v: hi/lo planes, [d][n] as u32 j-pairs
            float xh = __bfloat162float(__float2bfloat16(v.x));
            float yh = __bfloat162float(__float2bfloat16(v.y));
            float zh = __bfloat162float(__float2bfloat16(v.z));
            float wh = __bfloat162float(__float2bfloat16(v.w));
            size_t base = ((size_t)bh * ND + dd) * (NN / 2) + (n >> 1);
            g_vhi[base + 0] = pk_hi2(v.x, v.y);
            g_vhi[base + 1] = pk_hi2(v.z, v.w);
            g_vlo[base + 0] = pk_hi2(v.x - xh, v.y - yh);
            g_vlo[base + 1] = pk_hi2(v.z - zh, v.w - wh);
        }
    }
}

// ---------------------------------------------------------------------------
// Kernel 2: flash attention via mma.sync bf16 (fp32-exact split, no-max softmax).
// r9: 256 threads (8 warps x 16 rows), i-tile 128; double-buffered cp.async
// K/V stages; phase-separated GEMM1(+exp) then GEMM2 burst; pitch-36 smem;
// launch_bounds(256,2) -> 16 warps/SM.
// ---------------------------------------------------------------------------
__device__ __forceinline__ void fill_stage(
    unsigned (*ksS)[36], unsigned (*vhS)[36], unsigned (*vlS)[36],
    const unsigned* __restrict__ gk, const unsigned* __restrict__ gvh,
    const unsigned* __restrict__ gvl, int j0, int t)
{
#pragma unroll
    for (int i = 0; i < 2; i++) {              // K tile: 64x32 u32 = 512 16B chunks
        int c = t + i * 256;
        int row = c >> 3, col = (c & 7) * 4;
        cpa16(&ksS[row][col], &gk[(size_t)(j0 + row) * ND + col]);
    }
    {                                          // V hi/lo: 32x32 u32 each
        int row = t >> 3, col = (t & 7) * 4;
        cpa16(&vhS[row][col], &gvh[(size_t)row * (NN / 2) + (j0 >> 1) + col]);
        cpa16(&vlS[row][col], &gvl[(size_t)row * (NN / 2) + (j0 >> 1) + col]);
    }
}

__global__ __launch_bounds__(256, 2) void attn_kernel(float* __restrict__ out)
{
    __shared__ unsigned ks[2][64][36];   // [stage][j][d u32], pitch 36 (conflict-free)
    __shared__ unsigned vh[2][32][36];   // [stage][d][j-pair u32]
    __shared__ unsigned vl[2][32][36];

    int t    = threadIdx.x;
    int wid  = t >> 5, lane = t & 31;
    int g    = lane >> 2, tq = lane & 3;
    int bh   = blockIdx.x >> 3;
    int i0   = (blockIdx.x & 7) * 128;
    int rg   = i0 + wid * 16 + g;        // this thread's first fragment row

    const unsigned* gq  = g_qpk + (size_t)bh * NN * ND;
    const unsigned* gk  = g_kpk + (size_t)bh * NN * ND;
    const unsigned* gvh = g_vhi + (size_t)bh * ND * (NN / 2);
    const unsigned* gvl = g_vlo + (size_t)bh * ND * (NN / 2);

    // prologue: prefetch j-tile 0 into stage 0
    fill_stage(ks[0], vh[0], vl[0], gk, gvh, gvl, 0, t);
    CP_COMMIT();

    // Q A-fragments held all kernel: qa[kt*4 + {0..3}]
    unsigned qa[16];
#pragma unroll
    for (int kt = 0; kt < 4; kt++) {
        int c0 = kt * 8 + tq, c4 = c0 + 4;
        unsigned* a = &qa[kt * 4];
        a[0] = gq[(size_t)rg * ND + c0];
        a[1] = gq[(size_t)(rg + 8) * ND + c0];
        a[2] = gq[(size_t)rg * ND + c4];
        a[3] = gq[(size_t)(rg + 8) * ND + c4];
    }

    float oacc[16];
#pragma unroll
    for (int i = 0; i < 16; i++) oacc[i] = 0.f;
    float lsum[2] = {0.f, 0.f};          // rows g, g+8

    for (int jt = 0; jt < 16; ++jt) {
        int s = jt & 1;
        __syncthreads();                 // compute(jt-1) done before refilling its stage
        if (jt < 15) {
            fill_stage(ks[1 - s], vh[1 - s], vl[1 - s], gk, gvh, gvl, (jt + 1) * 64, t);
            CP_COMMIT();
            CP_WAIT(1);                  // fill(jt) landed
        } else {
            CP_WAIT(0);
        }
        __syncthreads();

        // ---- Phase 1: GEMM1 (S = qpk·kpk + qpk·ksw) + exp + P-frag build ----
        unsigned phi[16], plo[16];
#pragma unroll
        for (int nb = 0; nb < 8; nb++) {
            float c0 = 0.f, c1 = 0.f, c2 = 0.f, c3 = 0.f;
#pragma unroll
            for (int kt = 0; kt < 4; kt++) {
                unsigned b0 = ks[s][nb * 8 + g][kt * 8 + tq];
                unsigned b1 = ks[s][nb * 8 + g][kt * 8 + tq + 4];
                unsigned s0 = __byte_perm(b0, 0, 0x1032);   // swap-on-B
                unsigned s1 = __byte_perm(b1, 0, 0x1032);
                const unsigned* a = &qa[kt * 4];
                mma_bf16(c0, c1, c2, c3, a[0], a[1], a[2], a[3], b0, b1);
                mma_bf16(c0, c1, c2, c3, a[0], a[1], a[2], a[3], s0, s1);
            }
            float p0 = ex2(c0), p1 = ex2(c1), p2 = ex2(c2), p3 = ex2(c3);
            lsum[0] += p0 + p1;
            lsum[1] += p2 + p3;
            unsigned hp01 = pack2(p0, p1);
            unsigned hp23 = pack2(p2, p3);
            float h0 = __uint_as_float(hp01 << 16);
            float h1 = __uint_as_float(hp01 & 0xFFFF0000u);
            float h2 = __uint_as_float(hp23 << 16);
            float h3 = __uint_as_float(hp23 & 0xFFFF0000u);
            phi[nb * 2 + 0] = hp01;                       // row g
            phi[nb * 2 + 1] = hp23;                       // row g+8
            plo[nb * 2 + 0] = pack2(p0 - h0, p1 - h1);
            plo[nb * 2 + 1] = pack2(p2 - h2, p3 - h3);
        }

        // ---- Phase 2: GEMM2 burst: O += Phi·Vh + Phi·Vl + Plo·Vh ----
#pragma unroll
        for (int kt2 = 0; kt2 < 4; kt2++) {
            const unsigned* ah = &phi[kt2 * 4];
            const unsigned* al = &plo[kt2 * 4];
#pragma unroll
            for (int nb2 = 0; nb2 < 4; nb2++) {
                unsigned bh0 = vh[s][nb2 * 8 + g][kt2 * 8 + tq];
                unsigned bh1 = vh[s][nb2 * 8 + g][kt2 * 8 + tq + 4];
                unsigned bl0 = vl[s][nb2 * 8 + g][kt2 * 8 + tq];
                unsigned bl1 = vl[s][nb2 * 8 + g][kt2 * 8 + tq + 4];
                float* o = &oacc[nb2 * 4];
                mma_bf16(o[0], o[1], o[2], o[3], ah[0], ah[1], ah[2], ah[3], bh0, bh1);
                mma_bf16(o[0], o[1], o[2], o[3], ah[0], ah[1], ah[2], ah[3], bl0, bl1);
                mma_bf16(o[0], o[1], o[2], o[3], al[0], al[1], al[2], al[3], bh0, bh1);
            }
        }
    }

    // ---- finalize: quad-reduce row sums, divide, store ----
#pragma unroll
    for (int i = 0; i < 2; i++) {
        lsum[i] += __shfl_xor_sync(FULLM, lsum[i], 1);
        lsum[i] += __shfl_xor_sync(FULLM, lsum[i], 2);
    }
    int b = bh >> 2, h = bh & 3;
    size_t cbase = (size_t)b * NC + h * ND;
    float inv0 = 1.f / lsum[0];
    float inv1 = 1.f / lsum[1];
#pragma unroll
    for (int nb2 = 0; nb2 < 4; nb2++) {
        const float* o = &oacc[nb2 * 4];
        int d0 = nb2 * 8 + 2 * tq;
        out[(cbase + d0    ) * NN + rg    ] = o[0] * inv0;
        out[(cbase + d0 + 1) * NN + rg    ] = o[1] * inv0;
        out[(cbase + d0    ) * NN + rg + 8] = o[2] * inv1;
        out[(cbase + d0 + 1) * NN + rg + 8] = o[3] * inv1;
    }
}

extern "C" void kernel_launch(void* const* d_in, const int* in_sizes, int n_in,
                              void* d_out, int out_size)
{
    const float* x  = (const float*)d_in[0];
    const float* Wq = (const float*)d_in[1];
    const float* rw = (const float*)d_in[2];
    const float* rh = (const float*)d_in[3];
    float* out = (float*)d_out;

    dim3 g1(NN / 64, (3 * NC) / 64, NB);
    qkv_kernel<<<g1, 256>>>(x, Wq, rw, rh);

    attn_kernel<<<NBH * 8, 256>>>(out);   // 512 CTAs x 256 threads
}

// round 13
// speedup vs baseline: 1.3602x; 1.1606x over previous
#include <cuda_runtime.h>
#include <cuda_bf16.h>

#define NB 16
#define NC 128
#define NHEADS 4
#define ND 32
#define NN 1024
#define NBH (NB * NHEADS)
#define FULLM 0xFFFFFFFFu

// Static device scratch (allocation-free).
__device__ __align__(16) unsigned g_qpk[NBH * NN * ND];      // q packed (hi,lo) [bh][n][d]
__device__ __align__(16) unsigned g_kpk[NBH * NN * ND];      // k' packed       [bh][n][d]
__device__ __align__(16) unsigned g_vhi[NBH * ND * (NN / 2)];// v hi plane [bh][d][n-pair]
__device__ __align__(16) unsigned g_vlo[NBH * ND * (NN / 2)];// v lo plane
__device__ __align__(16) unsigned g_xpk[NB * NC * NN];       // x packed (hi,lo) [b][c][n]
__device__ __align__(16) unsigned g_wpk[3 * NC * NC];        // W packed (hi,lo) [o][c]

// ---------------- bf16 helpers ----------------
__device__ __forceinline__ unsigned pk_split(float x) {
    __nv_bfloat16 h = __float2bfloat16(x);
    float hf = __bfloat162float(h);
    __nv_bfloat16 l = __float2bfloat16(x - hf);
    return (unsigned)__bfloat16_as_ushort(h) | ((unsigned)__bfloat16_as_ushort(l) << 16);
}
__device__ __forceinline__ unsigned pk_hi2(float a, float b) {
    return (unsigned)__bfloat16_as_ushort(__float2bfloat16(a)) |
           ((unsigned)__bfloat16_as_ushort(__float2bfloat16(b)) << 16);
}
__device__ __forceinline__ unsigned pack2(float lo, float hi) {
    unsigned r;
    asm("cvt.rn.bf16x2.f32 %0, %1, %2;" : "=r"(r) : "f"(hi), "f"(lo));
    return r;
}
__device__ __forceinline__ float ex2(float x) {
    float y;
    asm("ex2.approx.ftz.f32 %0, %1;" : "=f"(y) : "f"(x));
    return y;
}

// m16n8k16 bf16 MMA, fp32 accumulate
__device__ __forceinline__ void mma_bf16(float& c0, float& c1, float& c2, float& c3,
                                         unsigned a0, unsigned a1, unsigned a2, unsigned a3,
                                         unsigned b0, unsigned b1) {
    asm volatile(
        "mma.sync.aligned.m16n8k16.row.col.f32.bf16.bf16.f32 "
        "{%0,%1,%2,%3}, {%4,%5,%6,%7}, {%8,%9}, {%0,%1,%2,%3};"
        : "+f"(c0), "+f"(c1), "+f"(c2), "+f"(c3)
        : "r"(a0), "r"(a1), "r"(a2), "r"(a3), "r"(b0), "r"(b1));
}

// ---------------- cp.async helpers ----------------
__device__ __forceinline__ void cpa16(void* dst, const void* src) {
    unsigned a = (unsigned)__cvta_generic_to_shared(dst);
    asm volatile("cp.async.cg.shared.global [%0], [%1], 16;" :: "r"(a), "l"(src));
}
#define CP_COMMIT() asm volatile("cp.async.commit_group;" ::: "memory")
#define CP_WAIT(n)  asm volatile("cp.async.wait_group %0;" :: "n"(n) : "memory")

// ---------------------------------------------------------------------------
// Kernel 0: elementwise prepack of x and W into (hi,lo)-bf16 u32.
// ---------------------------------------------------------------------------
#define NX (NB * NC * NN)
#define NW (3 * NC * NC)
__global__ __launch_bounds__(256) void pack_kernel(
    const float* __restrict__ x, const float* __restrict__ Wq)
{
    int idx = blockIdx.x * 256 + threadIdx.x;
    if (idx < NX) g_xpk[idx] = pk_split(x[idx]);
    else if (idx < NX + NW) g_wpk[idx - NX] = pk_split(Wq[idx - NX]);
}

// ---------------------------------------------------------------------------
// Kernel 1: QKV projection via mma.sync bf16 (exact split product) +
// relative-position fold into K + packed-output epilogue.
// CTA 256 thr (8 warps: 4 o-subtiles x 2 n-subtiles), tile o128 x n128.
// K=128 real c staged as 8 chunks of 16 u32, double-buffered cp.async.
// ---------------------------------------------------------------------------
__device__ __forceinline__ void qkv_fill(
    unsigned (*xsS)[136], unsigned (*wsS)[20],
    const unsigned* __restrict__ gx, int o0, int n0, int st, int t)
{
    int cu0 = st * 16;
#pragma unroll
    for (int i = 0; i < 2; i++) {          // x chunk: 16 c-rows x 128 n
        int idx = t + i * 256;
        int row = idx >> 5, ch = (idx & 31) * 4;
        cpa16(&xsS[row][ch], &gx[(size_t)(cu0 + row) * NN + n0 + ch]);
    }
#pragma unroll
    for (int i = 0; i < 2; i++) {          // W chunk: 128 o-rows x 16 u32
        int idx = t + i * 256;
        int row = idx >> 2, c4 = (idx & 3) * 4;
        cpa16(&wsS[row][c4], &g_wpk[(size_t)(o0 + row) * NC + cu0 + c4]);
    }
}

__global__ __launch_bounds__(256, 2) void qkv_kernel(
    const float* __restrict__ rw, const float* __restrict__ rh)
{
    __shared__ unsigned xs[2][16][136];   // [stage][c_u32][n], pitch 136: (8tq+g)%32 distinct
    __shared__ unsigned ws[2][128][20];   // [stage][o][c_u32], pitch 20: (20g+tq)%32 distinct

    int t = threadIdx.x;
    int wid = t >> 5, lane = t & 31;
    int g = lane >> 2, tq = lane & 3;
    int n0 = blockIdx.x * 128;
    int o0 = blockIdx.y * 128;
    int b  = blockIdx.z;
    int o_sub = (wid & 3) * 32;
    int n_sub = (wid >> 2) * 64;

    const unsigned* gx = g_xpk + (size_t)b * NC * NN;

    qkv_fill(xs[0], ws[0], gx, o0, n0, 0, t);
    CP_COMMIT();

    float acc[64];
#pragma unroll
    for (int i = 0; i < 64; i++) acc[i] = 0.f;

    for (int st = 0; st < 8; ++st) {
        int s = st & 1;
        __syncthreads();
        if (st < 7) {
            qkv_fill(xs[1 - s], ws[1 - s], gx, o0, n0, st + 1, t);
            CP_COMMIT();
            CP_WAIT(1);
        } else {
            CP_WAIT(0);
        }
        __syncthreads();

#pragma unroll
        for (int kc = 0; kc < 2; kc++) {
            unsigned a[2][4];
#pragma unroll
            for (int mb = 0; mb < 2; mb++) {
                int r0 = o_sub + mb * 16 + g;
                a[mb][0] = ws[s][r0    ][kc * 8 + tq];
                a[mb][1] = ws[s][r0 + 8][kc * 8 + tq];
                a[mb][2] = ws[s][r0    ][kc * 8 + tq + 4];
                a[mb][3] = ws[s][r0 + 8][kc * 8 + tq + 4];
            }
#pragma unroll
            for (int nb = 0; nb < 8; nb++) {
                unsigned b0 = xs[s][kc * 8 + tq    ][n_sub + nb * 8 + g];
                unsigned b1 = xs[s][kc * 8 + 4 + tq][n_sub + nb * 8 + g];
                unsigned s0 = __byte_perm(b0, 0, 0x1032);   // swap-on-B
                unsigned s1 = __byte_perm(b1, 0, 0x1032);
#pragma unroll
                for (int mb = 0; mb < 2; mb++) {
                    float* cc = &acc[(mb * 8 + nb) * 4];
                    mma_bf16(cc[0], cc[1], cc[2], cc[3],
                             a[mb][0], a[mb][1], a[mb][2], a[mb][3], b0, b1);
                    mma_bf16(cc[0], cc[1], cc[2], cc[3],
                             a[mb][0], a[mb][1], a[mb][2], a[mb][3], s0, s1);
                }
            }
        }
    }

    // ---- epilogue: scale/r-fold + pk_split stores ----
    const float qscale = 0.17677669529663689f * 1.4426950408889634f; // 1/sqrt(32)*log2e
    int s_type = o0 >> 7;                  // 0=q, 1=k, 2=v (uniform per CTA)
#pragma unroll
    for (int mb = 0; mb < 2; mb++) {
        int orow0 = o0 + o_sub + mb * 16 + g;
#pragma unroll
        for (int nb = 0; nb < 8; nb++) {
            const float* cc = &acc[(mb * 8 + nb) * 4];
            int n = n0 + n_sub + nb * 8 + 2 * tq;
#pragma unroll
            for (int half = 0; half < 2; half++) {
                int o = orow0 + half * 8;
                float v0 = cc[half * 2 + 0];
                float v1 = cc[half * 2 + 1];
                int oh = o & 127, h = oh >> 5, dd = oh & 31;
                int bhh = b * NHEADS + h;
                if (s_type == 0) {
                    v0 *= qscale; v1 *= qscale;
                    size_t base = ((size_t)bhh * NN + n) * ND + dd;
                    g_qpk[base]      = pk_split(v0);
                    g_qpk[base + ND] = pk_split(v1);
                } else if (s_type == 1) {
                    int rbase = (h * ND + dd) * 32;
                    float rhv = rh[rbase + (n >> 5)];      // n even: n,n+1 share hh
                    v0 += rw[rbase + (n & 31)] + rhv;
                    v1 += rw[rbase + ((n + 1) & 31)] + rhv;
                    size_t base = ((size_t)bhh * NN + n) * ND + dd;
                    g_kpk[base]      = pk_split(v0);
                    g_kpk[base + ND] = pk_split(v1);
                } else {
                    float h0 = __bfloat162float(__float2bfloat16(v0));
                    float h1 = __bfloat162float(__float2bfloat16(v1));
                    size_t base = ((size_t)bhh * ND + dd) * (NN / 2) + (n >> 1);
                    g_vhi[base] = pk_hi2(v0, v1);
                    g_vlo[base] = pk_hi2(v0 - h0, v1 - h1);
                }
            }
        }
    }
}

// ---------------------------------------------------------------------------
// Kernel 2: flash attention via mma.sync bf16 — UNCHANGED from r11 (88us).
// ---------------------------------------------------------------------------
__device__ __forceinline__ void fill_stage(
    unsigned (*ksS)[36], unsigned (*vhS)[36], unsigned (*vlS)[36],
    const unsigned* __restrict__ gk, const unsigned* __restrict__ gvh,
    const unsigned* __restrict__ gvl, int j0, int t)
{
#pragma unroll
    for (int i = 0; i < 2; i++) {
        int c = t + i * 256;
        int row = c >> 3, col = (c & 7) * 4;
        cpa16(&ksS[row][col], &gk[(size_t)(j0 + row) * ND + col]);
    }
    {
        int row = t >> 3, col = (t & 7) * 4;
        cpa16(&vhS[row][col], &gvh[(size_t)row * (NN / 2) + (j0 >> 1) + col]);
        cpa16(&vlS[row][col], &gvl[(size_t)row * (NN / 2) + (j0 >> 1) + col]);
    }
}

__global__ __launch_bounds__(256, 2) void attn_kernel(float* __restrict__ out)
{
    __shared__ unsigned ks[2][64][36];
    __shared__ unsigned vh[2][32][36];
    __shared__ unsigned vl[2][32][36];

    int t    = threadIdx.x;
    int wid  = t >> 5, lane = t & 31;
    int g    = lane >> 2, tq = lane & 3;
    int bh   = blockIdx.x >> 3;
    int i0   = (blockIdx.x & 7) * 128;
    int rg   = i0 + wid * 16 + g;

    const unsigned* gq  = g_qpk + (size_t)bh * NN * ND;
    const unsigned* gk  = g_kpk + (size_t)bh * NN * ND;
    const unsigned* gvh = g_vhi + (size_t)bh * ND * (NN / 2);
    const unsigned* gvl = g_vlo + (size_t)bh * ND * (NN / 2);

    fill_stage(ks[0], vh[0], vl[0], gk, gvh, gvl, 0, t);
    CP_COMMIT();

    unsigned qa[16];
#pragma unroll
    for (int kt = 0; kt < 4; kt++) {
        int c0 = kt * 8 + tq, c4 = c0 + 4;
        unsigned* a = &qa[kt * 4];
        a[0] = gq[(size_t)rg * ND + c0];
        a[1] = gq[(size_t)(rg + 8) * ND + c0];
        a[2] = gq[(size_t)rg * ND + c4];
        a[3] = gq[(size_t)(rg + 8) * ND + c4];
    }

    float oacc[16];
#pragma unroll
    for (int i = 0; i < 16; i++) oacc[i] = 0.f;
    float lsum[2] = {0.f, 0.f};

    for (int jt = 0; jt < 16; ++jt) {
        int s = jt & 1;
        __syncthreads();
        if (jt < 15) {
            fill_stage(ks[1 - s], vh[1 - s], vl[1 - s], gk, gvh, gvl, (jt + 1) * 64, t);
            CP_COMMIT();
            CP_WAIT(1);
        } else {
            CP_WAIT(0);
        }
        __syncthreads();

        unsigned phi[16], plo[16];
#pragma unroll
        for (int nb = 0; nb < 8; nb++) {
            float c0 = 0.f, c1 = 0.f, c2 = 0.f, c3 = 0.f;
#pragma unroll
            for (int kt = 0; kt < 4; kt++) {
                unsigned b0 = ks[s][nb * 8 + g][kt * 8 + tq];
                unsigned b1 = ks[s][nb * 8 + g][kt * 8 + tq + 4];
                unsigned s0 = __byte_perm(b0, 0, 0x1032);
                unsigned s1 = __byte_perm(b1, 0, 0x1032);
                const unsigned* a = &qa[kt * 4];
                mma_bf16(c0, c1, c2, c3, a[0], a[1], a[2], a[3], b0, b1);
                mma_bf16(c0, c1, c2, c3, a[0], a[1], a[2], a[3], s0, s1);
            }
            float p0 = ex2(c0), p1 = ex2(c1), p2 = ex2(c2), p3 = ex2(c3);
            lsum[0] += p0 + p1;
            lsum[1] += p2 + p3;
            unsigned hp01 = pack2(p0, p1);
            unsigned hp23 = pack2(p2, p3);
            float h0 = __uint_as_float(hp01 << 16);
            float h1 = __uint_as_float(hp01 & 0xFFFF0000u);
            float h2 = __uint_as_float(hp23 << 16);
            float h3 = __uint_as_float(hp23 & 0xFFFF0000u);
            phi[nb * 2 + 0] = hp01;
            phi[nb * 2 + 1] = hp23;
            plo[nb * 2 + 0] = pack2(p0 - h0, p1 - h1);
            plo[nb * 2 + 1] = pack2(p2 - h2, p3 - h3);
        }

#pragma unroll
        for (int kt2 = 0; kt2 < 4; kt2++) {
            const unsigned* ah = &phi[kt2 * 4];
            const unsigned* al = &plo[kt2 * 4];
#pragma unroll
            for (int nb2 = 0; nb2 < 4; nb2++) {
                unsigned bh0 = vh[s][nb2 * 8 + g][kt2 * 8 + tq];
                unsigned bh1 = vh[s][nb2 * 8 + g][kt2 * 8 + tq + 4];
                unsigned bl0 = vl[s][nb2 * 8 + g][kt2 * 8 + tq];
                unsigned bl1 = vl[s][nb2 * 8 + g][kt2 * 8 + tq + 4];
                float* o = &oacc[nb2 * 4];
                mma_bf16(o[0], o[1], o[2], o[3], ah[0], ah[1], ah[2], ah[3], bh0, bh1);
                mma_bf16(o[0], o[1], o[2], o[3], ah[0], ah[1], ah[2], ah[3], bl0, bl1);
                mma_bf16(o[0], o[1], o[2], o[3], al[0], al[1], al[2], al[3], bh0, bh1);
            }
        }
    }

#pragma unroll
    for (int i = 0; i < 2; i++) {
        lsum[i] += __shfl_xor_sync(FULLM, lsum[i], 1);
        lsum[i] += __shfl_xor_sync(FULLM, lsum[i], 2);
    }
    int b = bh >> 2, h = bh & 3;
    size_t cbase = (size_t)b * NC + h * ND;
    float inv0 = 1.f / lsum[0];
    float inv1 = 1.f / lsum[1];
#pragma unroll
    for (int nb2 = 0; nb2 < 4; nb2++) {
        const float* o = &oacc[nb2 * 4];
        int d0 = nb2 * 8 + 2 * tq;
        out[(cbase + d0    ) * NN + rg    ] = o[0] * inv0;
        out[(cbase + d0 + 1) * NN + rg    ] = o[1] * inv0;
        out[(cbase + d0    ) * NN + rg + 8] = o[2] * inv1;
        out[(cbase + d0 + 1) * NN + rg + 8] = o[3] * inv1;
    }
}

extern "C" void kernel_launch(void* const* d_in, const int* in_sizes, int n_in,
                              void* d_out, int out_size)
{
    const float* x  = (const float*)d_in[0];
    const float* Wq = (const float*)d_in[1];
    const float* rw = (const float*)d_in[2];
    const float* rh = (const float*)d_in[3];
    float* out = (float*)d_out;

    pack_kernel<<<(NX + NW) / 256, 256>>>(x, Wq);
    qkv_kernel<<<dim3(8, 3, 16), 256>>>(rw, rh);     // 384 CTAs
    attn_kernel<<<NBH * 8, 256>>>(out);              // 512 CTAs
}

// round 14
// speedup vs baseline: 1.7176x; 1.2627x over previous
#include <cuda_runtime.h>
#include <cuda_bf16.h>
#include <cuda_fp16.h>

#define NB 16
#define NC 128
#define NHEADS 4
#define ND 32
#define NN 1024
#define NBH (NB * NHEADS)
#define FULLM 0xFFFFFFFFu

// Static device scratch (allocation-free).
__device__ __align__(16) unsigned g_qpk[NBH * NN * ND];      // q packed (hi,lo) bf16 [bh][n][d]
__device__ __align__(16) unsigned g_kpk[NBH * NN * ND];      // k' packed             [bh][n][d]
__device__ __align__(16) unsigned g_v16[NBH * ND * (NN / 2)];// v fp16 plane [bh][d][n-pair]
__device__ __align__(16) unsigned g_xpk[NB * NC * NN];       // x packed (hi,lo) [b][c][n]
__device__ __align__(16) unsigned g_wpk[3 * NC * NC];        // W packed (hi,lo) [o][c]

// ---------------- pack helpers ----------------
__device__ __forceinline__ unsigned pk_split(float x) {
    __nv_bfloat16 h = __float2bfloat16(x);
    float hf = __bfloat162float(h);
    __nv_bfloat16 l = __float2bfloat16(x - hf);
    return (unsigned)__bfloat16_as_ushort(h) | ((unsigned)__bfloat16_as_ushort(l) << 16);
}
// fp16x2 with a in low bits
__device__ __forceinline__ unsigned pk_f16x2(float a, float b) {
    unsigned r;
    asm("cvt.rn.f16x2.f32 %0, %1, %2;" : "=r"(r) : "f"(b), "f"(a));
    return r;
}
__device__ __forceinline__ float ex2(float x) {
    float y;
    asm("ex2.approx.ftz.f32 %0, %1;" : "=f"(y) : "f"(x));
    return y;
}

// m16n8k16 bf16 MMA, fp32 accumulate
__device__ __forceinline__ void mma_bf16(float& c0, float& c1, float& c2, float& c3,
                                         unsigned a0, unsigned a1, unsigned a2, unsigned a3,
                                         unsigned b0, unsigned b1) {
    asm volatile(
        "mma.sync.aligned.m16n8k16.row.col.f32.bf16.bf16.f32 "
        "{%0,%1,%2,%3}, {%4,%5,%6,%7}, {%8,%9}, {%0,%1,%2,%3};"
        : "+f"(c0), "+f"(c1), "+f"(c2), "+f"(c3)
        : "r"(a0), "r"(a1), "r"(a2), "r"(a3), "r"(b0), "r"(b1));
}
// m16n8k16 fp16 MMA, fp32 accumulate
__device__ __forceinline__ void mma_f16(float& c0, float& c1, float& c2, float& c3,
                                        unsigned a0, unsigned a1, unsigned a2, unsigned a3,
                                        unsigned b0, unsigned b1) {
    asm volatile(
        "mma.sync.aligned.m16n8k16.row.col.f32.f16.f16.f32 "
        "{%0,%1,%2,%3}, {%4,%5,%6,%7}, {%8,%9}, {%0,%1,%2,%3};"
        : "+f"(c0), "+f"(c1), "+f"(c2), "+f"(c3)
        : "r"(a0), "r"(a1), "r"(a2), "r"(a3), "r"(b0), "r"(b1));
}

// ---------------- cp.async helpers ----------------
__device__ __forceinline__ void cpa16(void* dst, const void* src) {
    unsigned a = (unsigned)__cvta_generic_to_shared(dst);
    asm volatile("cp.async.cg.shared.global [%0], [%1], 16;" :: "r"(a), "l"(src));
}
#define CP_COMMIT() asm volatile("cp.async.commit_group;" ::: "memory")
#define CP_WAIT(n)  asm volatile("cp.async.wait_group %0;" :: "n"(n) : "memory")

// ---------------------------------------------------------------------------
// Kernel 0: vectorized prepack of x and W into (hi,lo)-bf16 u32.
// ---------------------------------------------------------------------------
#define NX (NB * NC * NN)
#define NW (3 * NC * NC)
__global__ __launch_bounds__(256) void pack_kernel(
    const float* __restrict__ x, const float* __restrict__ Wq)
{
    int idx = blockIdx.x * 256 + threadIdx.x;
    if (idx < NX / 4) {
        float4 v = *(const float4*)&x[idx * 4];
        uint4 o;
        o.x = pk_split(v.x); o.y = pk_split(v.y);
        o.z = pk_split(v.z); o.w = pk_split(v.w);
        *(uint4*)&g_xpk[idx * 4] = o;
    } else if (idx < NX / 4 + NW / 4) {
        int j = idx - NX / 4;
        float4 v = *(const float4*)&Wq[j * 4];
        uint4 o;
        o.x = pk_split(v.x); o.y = pk_split(v.y);
        o.z = pk_split(v.z); o.w = pk_split(v.w);
        *(uint4*)&g_wpk[j * 4] = o;
    }
}

// ---------------------------------------------------------------------------
// Kernel 1: QKV projection via mma.sync bf16 (exact split product) +
// relative-position fold into K + packed-output epilogue.
// ---------------------------------------------------------------------------
__device__ __forceinline__ void qkv_fill(
    unsigned (*xsS)[136], unsigned (*wsS)[20],
    const unsigned* __restrict__ gx, int o0, int n0, int st, int t)
{
    int cu0 = st * 16;
#pragma unroll
    for (int i = 0; i < 2; i++) {          // x chunk: 16 c-rows x 128 n
        int idx = t + i * 256;
        int row = idx >> 5, ch = (idx & 31) * 4;
        cpa16(&xsS[row][ch], &gx[(size_t)(cu0 + row) * NN + n0 + ch]);
    }
#pragma unroll
    for (int i = 0; i < 2; i++) {          // W chunk: 128 o-rows x 16 u32
        int idx = t + i * 256;
        int row = idx >> 2, c4 = (idx & 3) * 4;
        cpa16(&wsS[row][c4], &g_wpk[(size_t)(o0 + row) * NC + cu0 + c4]);
    }
}

__global__ __launch_bounds__(256, 2) void qkv_kernel(
    const float* __restrict__ rw, const float* __restrict__ rh)
{
    __shared__ unsigned xs[2][16][136];   // [stage][c_u32][n]
    __shared__ unsigned ws[2][128][20];   // [stage][o][c_u32]

    int t = threadIdx.x;
    int wid = t >> 5, lane = t & 31;
    int g = lane >> 2, tq = lane & 3;
    int n0 = blockIdx.x * 128;
    int o0 = blockIdx.y * 128;
    int b  = blockIdx.z;
    int o_sub = (wid & 3) * 32;
    int n_sub = (wid >> 2) * 64;

    const unsigned* gx = g_xpk + (size_t)b * NC * NN;

    qkv_fill(xs[0], ws[0], gx, o0, n0, 0, t);
    CP_COMMIT();

    float acc[64];
#pragma unroll
    for (int i = 0; i < 64; i++) acc[i] = 0.f;

    for (int st = 0; st < 8; ++st) {
        int s = st & 1;
        __syncthreads();
        if (st < 7) {
            qkv_fill(xs[1 - s], ws[1 - s], gx, o0, n0, st + 1, t);
            CP_COMMIT();
            CP_WAIT(1);
        } else {
            CP_WAIT(0);
        }
        __syncthreads();

#pragma unroll
        for (int kc = 0; kc < 2; kc++) {
            unsigned a[2][4];
#pragma unroll
            for (int mb = 0; mb < 2; mb++) {
                int r0 = o_sub + mb * 16 + g;
                a[mb][0] = ws[s][r0    ][kc * 8 + tq];
                a[mb][1] = ws[s][r0 + 8][kc * 8 + tq];
                a[mb][2] = ws[s][r0    ][kc * 8 + tq + 4];
                a[mb][3] = ws[s][r0 + 8][kc * 8 + tq + 4];
            }
#pragma unroll
            for (int nb = 0; nb < 8; nb++) {
                unsigned b0 = xs[s][kc * 8 + tq    ][n_sub + nb * 8 + g];
                unsigned b1 = xs[s][kc * 8 + 4 + tq][n_sub + nb * 8 + g];
                unsigned s0 = __byte_perm(b0, 0, 0x1032);   // swap-on-B
                unsigned s1 = __byte_perm(b1, 0, 0x1032);
#pragma unroll
                for (int mb = 0; mb < 2; mb++) {
                    float* cc = &acc[(mb * 8 + nb) * 4];
                    mma_bf16(cc[0], cc[1], cc[2], cc[3],
                             a[mb][0], a[mb][1], a[mb][2], a[mb][3], b0, b1);
                    mma_bf16(cc[0], cc[1], cc[2], cc[3],
                             a[mb][0], a[mb][1], a[mb][2], a[mb][3], s0, s1);
                }
            }
        }
    }

    // ---- epilogue: scale/r-fold + packed stores ----
    const float qscale = 0.17677669529663689f * 1.4426950408889634f; // 1/sqrt(32)*log2e
    int s_type = o0 >> 7;                  // 0=q, 1=k, 2=v (uniform per CTA)
#pragma unroll
    for (int mb = 0; mb < 2; mb++) {
        int orow0 = o0 + o_sub + mb * 16 + g;
#pragma unroll
        for (int nb = 0; nb < 8; nb++) {
            const float* cc = &acc[(mb * 8 + nb) * 4];
            int n = n0 + n_sub + nb * 8 + 2 * tq;
#pragma unroll
            for (int half = 0; half < 2; half++) {
                int o = orow0 + half * 8;
                float v0 = cc[half * 2 + 0];
                float v1 = cc[half * 2 + 1];
                int oh = o & 127, h = oh >> 5, dd = oh & 31;
                int bhh = b * NHEADS + h;
                if (s_type == 0) {
                    v0 *= qscale; v1 *= qscale;
                    size_t base = ((size_t)bhh * NN + n) * ND + dd;
                    g_qpk[base]      = pk_split(v0);
                    g_qpk[base + ND] = pk_split(v1);
                } else if (s_type == 1) {
                    int rbase = (h * ND + dd) * 32;
                    float rhv = rh[rbase + (n >> 5)];      // n even: n,n+1 share hh
                    v0 += rw[rbase + (n & 31)] + rhv;
                    v1 += rw[rbase + ((n + 1) & 31)] + rhv;
                    size_t base = ((size_t)bhh * NN + n) * ND + dd;
                    g_kpk[base]      = pk_split(v0);
                    g_kpk[base + ND] = pk_split(v1);
                } else {
                    size_t base = ((size_t)bhh * ND + dd) * (NN / 2) + (n >> 1);
                    g_v16[base] = pk_f16x2(v0, v1);        // fp16 plane
                }
            }
        }
    }
}

// ---------------------------------------------------------------------------
// Kernel 2: flash attention. GEMM1 bf16-split (exact); GEMM2 plain fp16
// (P scaled by 2^-4 in log2 domain for fp16 range; lsum cancels the shift).
// ---------------------------------------------------------------------------
__device__ __forceinline__ void fill_stage(
    unsigned (*ksS)[36], unsigned (*vhS)[36],
    const unsigned* __restrict__ gk, const unsigned* __restrict__ gv,
    int j0, int t)
{
#pragma unroll
    for (int i = 0; i < 2; i++) {          // K tile: 64x32 u32
        int c = t + i * 256;
        int row = c >> 3, col = (c & 7) * 4;
        cpa16(&ksS[row][col], &gk[(size_t)(j0 + row) * ND + col]);
    }
    {                                      // V fp16 tile: 32x32 u32
        int row = t >> 3, col = (t & 7) * 4;
        cpa16(&vhS[row][col], &gv[(size_t)row * (NN / 2) + (j0 >> 1) + col]);
    }
}

__global__ __launch_bounds__(256, 2) void attn_kernel(float* __restrict__ out)
{
    __shared__ unsigned ks[2][64][36];
    __shared__ unsigned vh[2][32][36];

    int t    = threadIdx.x;
    int wid  = t >> 5, lane = t & 31;
    int g    = lane >> 2, tq = lane & 3;
    int bh   = blockIdx.x >> 3;
    int i0   = (blockIdx.x & 7) * 128;
    int rg   = i0 + wid * 16 + g;

    const unsigned* gq = g_qpk + (size_t)bh * NN * ND;
    const unsigned* gk = g_kpk + (size_t)bh * NN * ND;
    const unsigned* gv = g_v16 + (size_t)bh * ND * (NN / 2);

    fill_stage(ks[0], vh[0], gk, gv, 0, t);
    CP_COMMIT();

    unsigned qa[16];
#pragma unroll
    for (int kt = 0; kt < 4; kt++) {
        int c0 = kt * 8 + tq, c4 = c0 + 4;
        unsigned* a = &qa[kt * 4];
        a[0] = gq[(size_t)rg * ND + c0];
        a[1] = gq[(size_t)(rg + 8) * ND + c0];
        a[2] = gq[(size_t)rg * ND + c4];
        a[3] = gq[(size_t)(rg + 8) * ND + c4];
    }

    float oacc[16];
#pragma unroll
    for (int i = 0; i < 16; i++) oacc[i] = 0.f;
    float lsum[2] = {0.f, 0.f};

    for (int jt = 0; jt < 16; ++jt) {
        int s = jt & 1;
        __syncthreads();
        if (jt < 15) {
            fill_stage(ks[1 - s], vh[1 - s], gk, gv, (jt + 1) * 64, t);
            CP_COMMIT();
            CP_WAIT(1);
        } else {
            CP_WAIT(0);
        }
        __syncthreads();

        // ---- Phase 1: GEMM1 + exp(2^(c-4)) + fp16 P-fragments ----
        unsigned phi[16];
#pragma unroll
        for (int nb = 0; nb < 8; nb++) {
            float c0 = 0.f, c1 = 0.f, c2 = 0.f, c3 = 0.f;
#pragma unroll
            for (int kt = 0; kt < 4; kt++) {
                unsigned b0 = ks[s][nb * 8 + g][kt * 8 + tq];
                unsigned b1 = ks[s][nb * 8 + g][kt * 8 + tq + 4];
                unsigned s0 = __byte_perm(b0, 0, 0x1032);
                unsigned s1 = __byte_perm(b1, 0, 0x1032);
                const unsigned* a = &qa[kt * 4];
                mma_bf16(c0, c1, c2, c3, a[0], a[1], a[2], a[3], b0, b1);
                mma_bf16(c0, c1, c2, c3, a[0], a[1], a[2], a[3], s0, s1);
            }
            // shift by -4 in log2 domain: keeps P within fp16 range (lsum cancels it)
            float p0 = ex2(c0 - 4.f), p1 = ex2(c1 - 4.f);
            float p2 = ex2(c2 - 4.f), p3 = ex2(c3 - 4.f);
            lsum[0] += p0 + p1;
            lsum[1] += p2 + p3;
            phi[nb * 2 + 0] = pk_f16x2(p0, p1);   // row g
            phi[nb * 2 + 1] = pk_f16x2(p2, p3);   // row g+8
        }

        // ---- Phase 2: GEMM2 burst (fp16): O += P · V^T ----
#pragma unroll
        for (int kt2 = 0; kt2 < 4; kt2++) {
            const unsigned* ah = &phi[kt2 * 4];
#pragma unroll
            for (int nb2 = 0; nb2 < 4; nb2++) {
                unsigned bh0 = vh[s][nb2 * 8 + g][kt2 * 8 + tq];
                unsigned bh1 = vh[s][nb2 * 8 + g][kt2 * 8 + tq + 4];
                float* o = &oacc[nb2 * 4];
                mma_f16(o[0], o[1], o[2], o[3], ah[0], ah[1], ah[2], ah[3], bh0, bh1);
            }
        }
    }

#pragma unroll
    for (int i = 0; i < 2; i++) {
        lsum[i] += __shfl_xor_sync(FULLM, lsum[i], 1);
        lsum[i] += __shfl_xor_sync(FULLM, lsum[i], 2);
    }
    int b = bh >> 2, h = bh & 3;
    size_t cbase = (size_t)b * NC + h * ND;
    float inv0 = 1.f / lsum[0];
    float inv1 = 1.f / lsum[1];
#pragma unroll
    for (int nb2 = 0; nb2 < 4; nb2++) {
        const float* o = &oacc[nb2 * 4];
        int d0 = nb2 * 8 + 2 * tq;
        out[(cbase + d0    ) * NN + rg    ] = o[0] * inv0;
        out[(cbase + d0 + 1) * NN + rg    ] = o[1] * inv0;
        out[(cbase + d0    ) * NN + rg + 8] = o[2] * inv1;
        out[(cbase + d0 + 1) * NN + rg + 8] = o[3] * inv1;
    }
}

extern "C" void kernel_launch(void* const* d_in, const int* in_sizes, int n_in,
                              void* d_out, int out_size)
{
    const float* x  = (const float*)d_in[0];
    const float* Wq = (const float*)d_in[1];
    const float* rw = (const float*)d_in[2];
    const float* rh = (const float*)d_in[3];
    float* out = (float*)d_out;

    pack_kernel<<<((NX + NW) / 4 + 255) / 256, 256>>>(x, Wq);
    qkv_kernel<<<dim3(8, 3, 16), 256>>>(rw, rh);     // 384 CTAs
    attn_kernel<<<NBH * 8, 256>>>(out);              // 512 CTAs
}

// round 17
// speedup vs baseline: 1.8215x; 1.0605x over previous
#include <cuda_runtime.h>
#include <cuda_bf16.h>
#include <cuda_fp16.h>

#define NB 16
#define NC 128
#define NHEADS 4
#define ND 32
#define NN 1024
#define NBH (NB * NHEADS)
#define FULLM 0xFFFFFFFFu

// Static device scratch (allocation-free). Separate hi/lo bf16 planes.
// q,k planes: bf16 [bh][n][d] viewed as u32 [bh][n][16] (d-pairs)
__device__ __align__(16) unsigned g_qh[NBH * NN * 16];
__device__ __align__(16) unsigned g_ql[NBH * NN * 16];
__device__ __align__(16) unsigned g_kh[NBH * NN * 16];
__device__ __align__(16) unsigned g_kl[NBH * NN * 16];
__device__ __align__(16) unsigned g_v16[NBH * ND * (NN / 2)];  // v fp16 [bh][d][n-pair]
// x planes: u32 [b][c-pair][n] (pair along c); W planes: u32 [o][c-pair]
__device__ __align__(16) unsigned g_xh[NB * 64 * NN];
__device__ __align__(16) unsigned g_xl[NB * 64 * NN];
__device__ __align__(16) unsigned g_wh[3 * NC * 64];
__device__ __align__(16) unsigned g_wl[3 * NC * 64];

// ---------------- helpers ----------------
__device__ __forceinline__ unsigned short bh16(float x) {
    return __bfloat16_as_ushort(__float2bfloat16(x));
}
__device__ __forceinline__ float bh16f(unsigned short u) {
    return __bfloat162float(__ushort_as_bfloat16(u));
}
// u32 = (bf16(a) low, bf16(b) high)  [K elements 2p, 2p+1]
__device__ __forceinline__ unsigned pk_bf2(float a, float b) {
    unsigned r;
    asm("cvt.rn.bf16x2.f32 %0, %1, %2;" : "=r"(r) : "f"(b), "f"(a));
    return r;
}
__device__ __forceinline__ unsigned pk_f16x2(float a, float b) {
    unsigned r;
    asm("cvt.rn.f16x2.f32 %0, %1, %2;" : "=r"(r) : "f"(b), "f"(a));
    return r;
}
__device__ __forceinline__ float ex2(float x) {
    float y;
    asm("ex2.approx.ftz.f32 %0, %1;" : "=f"(y) : "f"(x));
    return y;
}

__device__ __forceinline__ void mma_bf16(float& c0, float& c1, float& c2, float& c3,
                                         unsigned a0, unsigned a1, unsigned a2, unsigned a3,
                                         unsigned b0, unsigned b1) {
    asm volatile(
        "mma.sync.aligned.m16n8k16.row.col.f32.bf16.bf16.f32 "
        "{%0,%1,%2,%3}, {%4,%5,%6,%7}, {%8,%9}, {%0,%1,%2,%3};"
        : "+f"(c0), "+f"(c1), "+f"(c2), "+f"(c3)
        : "r"(a0), "r"(a1), "r"(a2), "r"(a3), "r"(b0), "r"(b1));
}
__device__ __forceinline__ void mma_f16(float& c0, float& c1, float& c2, float& c3,
                                        unsigned a0, unsigned a1, unsigned a2, unsigned a3,
                                        unsigned b0, unsigned b1) {
    asm volatile(
        "mma.sync.aligned.m16n8k16.row.col.f32.f16.f16.f32 "
        "{%0,%1,%2,%3}, {%4,%5,%6,%7}, {%8,%9}, {%0,%1,%2,%3};"
        : "+f"(c0), "+f"(c1), "+f"(c2), "+f"(c3)
        : "r"(a0), "r"(a1), "r"(a2), "r"(a3), "r"(b0), "r"(b1));
}

__device__ __forceinline__ void cpa16(void* dst, const void* src) {
    unsigned a = (unsigned)__cvta_generic_to_shared(dst);
    asm volatile("cp.async.cg.shared.global [%0], [%1], 16;" :: "r"(a), "l"(src));
}
#define CP_COMMIT() asm volatile("cp.async.commit_group;" ::: "memory")
#define CP_WAIT(n)  asm volatile("cp.async.wait_group %0;" :: "n"(n) : "memory")

// ---------------------------------------------------------------------------
// Kernel 0: prepack x and W into hi/lo bf16 planes (pairs along c).
// ---------------------------------------------------------------------------
#define XTHREADS (NB * 64 * 256)     // each: 1 c-pair x 4 n
#define WTHREADS (3 * NC * 32)       // each: 1 o x 4 c
__global__ __launch_bounds__(256) void pack_kernel(
    const float* __restrict__ x, const float* __restrict__ Wq)
{
    int idx = blockIdx.x * 256 + threadIdx.x;
    if (idx < XTHREADS) {
        int b  = idx >> 14;            // / (64*256)
        int cp = (idx >> 8) & 63;
        int n  = (idx & 255) * 4;
        const float* r0 = &x[((size_t)b * NC + 2 * cp) * NN + n];
        const float* r1 = r0 + NN;
        float4 a = *(const float4*)r0;
        float4 c = *(const float4*)r1;
        uint4 oh, ol;
        float* pa = (float*)&a; float* pc = (float*)&c;
        unsigned* poh = (unsigned*)&oh; unsigned* pol = (unsigned*)&ol;
#pragma unroll
        for (int i = 0; i < 4; i++) {
            float v0 = pa[i], v1 = pc[i];
            unsigned short h0 = bh16(v0), h1 = bh16(v1);
            poh[i] = (unsigned)h0 | ((unsigned)h1 << 16);
            pol[i] = (unsigned)bh16(v0 - bh16f(h0)) | ((unsigned)bh16(v1 - bh16f(h1)) << 16);
        }
        size_t o = ((size_t)b * 64 + cp) * NN + n;
        *(uint4*)&g_xh[o] = oh;
        *(uint4*)&g_xl[o] = ol;
    } else if (idx < XTHREADS + WTHREADS) {
        int j = idx - XTHREADS;
        int o = j >> 5, c4 = (j & 31) * 4;
        float4 w = *(const float4*)&Wq[o * NC + c4];
        unsigned short h0 = bh16(w.x), h1 = bh16(w.y), h2 = bh16(w.z), h3 = bh16(w.w);
        uint2 oh, ol;
        oh.x = (unsigned)h0 | ((unsigned)h1 << 16);
        oh.y = (unsigned)h2 | ((unsigned)h3 << 16);
        ol.x = (unsigned)bh16(w.x - bh16f(h0)) | ((unsigned)bh16(w.y - bh16f(h1)) << 16);
        ol.y = (unsigned)bh16(w.z - bh16f(h2)) | ((unsigned)bh16(w.w - bh16f(h3)) << 16);
        size_t d = (size_t)o * 64 + c4 / 2;
        *(uint2*)&g_wh[d] = oh;
        *(uint2*)&g_wl[d] = ol;
    }
}

// ---------------------------------------------------------------------------
// Kernel 1: QKV projection, 3-term split MMA (Wh·xh + Wh·xl + Wl·xh).
// CTA 256 thr (8 warps: 4 o-sub x 2 n-sub), tile o128 x n128, 8 K-stages of 16c.
// ---------------------------------------------------------------------------
__device__ __forceinline__ void qkv_fill(
    unsigned (*xhS)[136], unsigned (*xlS)[136],
    unsigned (*whS)[12],  unsigned (*wlS)[12],
    int b, int o0, int n0, int st, int t)
{
    {   // x planes: 8 c-pair rows x 128 u32
        int row = t >> 5, col = (t & 31) * 4;
        size_t src = ((size_t)b * 64 + st * 8 + row) * NN + n0 + col;
        cpa16(&xhS[row][col], &g_xh[src]);
        cpa16(&xlS[row][col], &g_xl[src]);
    }
    {   // W planes: 128 o rows x 8 u32
        int row = t >> 1, col = (t & 1) * 4;
        size_t src = (size_t)(o0 + row) * 64 + st * 8 + col;
        cpa16(&whS[row][col], &g_wh[src]);
        cpa16(&wlS[row][col], &g_wl[src]);
    }
}

__global__ __launch_bounds__(256, 2) void qkv_kernel(
    const float* __restrict__ rw, const float* __restrict__ rh)
{
    __shared__ unsigned xsh[2][8][136], xsl[2][8][136];   // bank: 8tq+g distinct
    __shared__ unsigned wsh[2][128][12], wsl[2][128][12]; // bank: 12g+tq distinct

    int t = threadIdx.x;
    int wid = t >> 5, lane = t & 31;
    int g = lane >> 2, tq = lane & 3;
    int n0 = blockIdx.x * 128;
    int o0 = blockIdx.y * 128;
    int b  = blockIdx.z;
    int o_sub = (wid & 3) * 32;
    int n_sub = (wid >> 2) * 64;

    qkv_fill(xsh[0], xsl[0], wsh[0], wsl[0], b, o0, n0, 0, t);
    CP_COMMIT();

    float acc[64];
#pragma unroll
    for (int i = 0; i < 64; i++) acc[i] = 0.f;

    for (int st = 0; st < 8; ++st) {
        int s = st & 1;
        __syncthreads();
        if (st < 7) {
            qkv_fill(xsh[1 - s], xsl[1 - s], wsh[1 - s], wsl[1 - s], b, o0, n0, st + 1, t);
            CP_COMMIT();
            CP_WAIT(1);
        } else {
            CP_WAIT(0);
        }
        __syncthreads();

        unsigned ah[2][4], al[2][4];
#pragma unroll
        for (int mb = 0; mb < 2; mb++) {
            int r0 = o_sub + mb * 16 + g;
            ah[mb][0] = wsh[s][r0    ][tq];
            ah[mb][1] = wsh[s][r0 + 8][tq];
            ah[mb][2] = wsh[s][r0    ][tq + 4];
            ah[mb][3] = wsh[s][r0 + 8][tq + 4];
            al[mb][0] = wsl[s][r0    ][tq];
            al[mb][1] = wsl[s][r0 + 8][tq];
            al[mb][2] = wsl[s][r0    ][tq + 4];
            al[mb][3] = wsl[s][r0 + 8][tq + 4];
        }
#pragma unroll
        for (int nb = 0; nb < 8; nb++) {
            int ncol = n_sub + nb * 8 + g;
            unsigned bh0 = xsh[s][tq    ][ncol];
            unsigned bh1 = xsh[s][tq + 4][ncol];
            unsigned bl0 = xsl[s][tq    ][ncol];
            unsigned bl1 = xsl[s][tq + 4][ncol];
#pragma unroll
            for (int mb = 0; mb < 2; mb++) {
                float* cc = &acc[(mb * 8 + nb) * 4];
                mma_bf16(cc[0], cc[1], cc[2], cc[3],
                         ah[mb][0], ah[mb][1], ah[mb][2], ah[mb][3], bh0, bh1);
                mma_bf16(cc[0], cc[1], cc[2], cc[3],
                         ah[mb][0], ah[mb][1], ah[mb][2], ah[mb][3], bl0, bl1);
                mma_bf16(cc[0], cc[1], cc[2], cc[3],
                         al[mb][0], al[mb][1], al[mb][2], al[mb][3], bh0, bh1);
            }
        }
    }

    // ---- epilogue: scale/r-fold + plane stores ----
    const float qscale = 0.17677669529663689f * 1.4426950408889634f; // 1/sqrt(32)*log2e
    int s_type = o0 >> 7;
    unsigned short* qh16 = (unsigned short*)g_qh;
    unsigned short* ql16 = (unsigned short*)g_ql;
    unsigned short* kh16 = (unsigned short*)g_kh;
    unsigned short* kl16 = (unsigned short*)g_kl;
#pragma unroll
    for (int mb = 0; mb < 2; mb++) {
        int orow0 = o0 + o_sub + mb * 16 + g;
#pragma unroll
        for (int nb = 0; nb < 8; nb++) {
            const float* cc = &acc[(mb * 8 + nb) * 4];
            int n = n0 + n_sub + nb * 8 + 2 * tq;
#pragma unroll
            for (int half = 0; half < 2; half++) {
                int o = orow0 + half * 8;
                float v0 = cc[half * 2 + 0];
                float v1 = cc[half * 2 + 1];
                int oh = o & 127, h = oh >> 5, dd = oh & 31;
                int bhh = b * NHEADS + h;
                if (s_type == 0) {
                    v0 *= qscale; v1 *= qscale;
                    size_t base = ((size_t)bhh * NN + n) * 32 + dd;
                    unsigned short h0 = bh16(v0), h1 = bh16(v1);
                    qh16[base]      = h0;
                    qh16[base + 32] = h1;
                    ql16[base]      = bh16(v0 - bh16f(h0));
                    ql16[base + 32] = bh16(v1 - bh16f(h1));
                } else if (s_type == 1) {
                    int rbase = (h * ND + dd) * 32;
                    float rhv = rh[rbase + (n >> 5)];   // n even: n,n+1 share hh
                    v0 += rw[rbase + (n & 31)] + rhv;
                    v1 += rw[rbase + ((n + 1) & 31)] + rhv;
                    size_t base = ((size_t)bhh * NN + n) * 32 + dd;
                    unsigned short h0 = bh16(v0), h1 = bh16(v1);
                    kh16[base]      = h0;
                    kh16[base + 32] = h1;
                    kl16[base]      = bh16(v0 - bh16f(h0));
                    kl16[base + 32] = bh16(v1 - bh16f(h1));
                } else {
                    size_t base = ((size_t)bhh * ND + dd) * (NN / 2) + (n >> 1);
                    g_v16[base] = pk_f16x2(v0, v1);
                }
            }
        }
    }
}

// ---------------------------------------------------------------------------
// Kernel 2: flash attention. GEMM1 = 3-term bf16 split (qh·kh+qh·kl+ql·kh);
// GEMM2 = fp16 (P shifted by 2^-4 in log2 domain; lsum cancels the shift).
// ---------------------------------------------------------------------------
__device__ __forceinline__ void fill_stage(
    unsigned (*khS)[20], unsigned (*klS)[20], unsigned (*vhS)[36],
    const unsigned* __restrict__ gkh, const unsigned* __restrict__ gkl,
    const unsigned* __restrict__ gv, int j0, int t)
{
    {   // k planes: 64 rows x 16 u32 each
        int row = t >> 2, col = (t & 3) * 4;
        size_t src = (size_t)(j0 + row) * 16 + col;
        cpa16(&khS[row][col], &gkh[src]);
        cpa16(&klS[row][col], &gkl[src]);
    }
    {   // v fp16: 32 rows x 32 u32
        int row = t >> 3, col = (t & 7) * 4;
        cpa16(&vhS[row][col], &gv[(size_t)row * (NN / 2) + (j0 >> 1) + col]);
    }
}

__global__ __launch_bounds__(256, 2) void attn_kernel(float* __restrict__ out)
{
    __shared__ unsigned ksh[2][64][20], ksl[2][64][20];  // bank: 20g+tq distinct
    __shared__ unsigned vh[2][32][36];

    int t    = threadIdx.x;
    int wid  = t >> 5, lane = t & 31;
    int g    = lane >> 2, tq = lane & 3;
    int bh   = blockIdx.x >> 3;
    int i0   = (blockIdx.x & 7) * 128;
    int rg   = i0 + wid * 16 + g;

    const unsigned* gqh = g_qh + (size_t)bh * NN * 16;
    const unsigned* gql = g_ql + (size_t)bh * NN * 16;
    const unsigned* gkh = g_kh + (size_t)bh * NN * 16;
    const unsigned* gkl = g_kl + (size_t)bh * NN * 16;
    const unsigned* gv  = g_v16 + (size_t)bh * ND * (NN / 2);

    fill_stage(ksh[0], ksl[0], vh[0], gkh, gkl, gv, 0, t);
    CP_COMMIT();

    // Q fragments: hi and lo planes, 2 K16 chunks over d=32
    unsigned qah[8], qal[8];
#pragma unroll
    for (int kt = 0; kt < 2; kt++) {
        int c0 = kt * 8 + tq, c4 = c0 + 4;
        qah[kt * 4 + 0] = gqh[(size_t)rg * 16 + c0];
        qah[kt * 4 + 1] = gqh[(size_t)(rg + 8) * 16 + c0];
        qah[kt * 4 + 2] = gqh[(size_t)rg * 16 + c4];
        qah[kt * 4 + 3] = gqh[(size_t)(rg + 8) * 16 + c4];
        qal[kt * 4 + 0] = gql[(size_t)rg * 16 + c0];
        qal[kt * 4 + 1] = gql[(size_t)(rg + 8) * 16 + c0];
        qal[kt * 4 + 2] = gql[(size_t)rg * 16 + c4];
        qal[kt * 4 + 3] = gql[(size_t)(rg + 8) * 16 + c4];
    }

    float oacc[16];
#pragma unroll
    for (int i = 0; i < 16; i++) oacc[i] = 0.f;
    float lsum[2] = {0.f, 0.f};

    for (int jt = 0; jt < 16; ++jt) {
        int s = jt & 1;
        __syncthreads();
        if (jt < 15) {
            fill_stage(ksh[1 - s], ksl[1 - s], vh[1 - s], gkh, gkl, gv, (jt + 1) * 64, t);
            CP_COMMIT();
            CP_WAIT(1);
        } else {
            CP_WAIT(0);
        }
        __syncthreads();

        // ---- Phase 1: 3-term GEMM1 + exp + fp16 P-fragments ----
        unsigned phi[16];
#pragma unroll
        for (int nb = 0; nb < 8; nb++) {
            int jrow = nb * 8 + g;
            float c0 = 0.f, c1 = 0.f, c2 = 0.f, c3 = 0.f;
#pragma unroll
            for (int kt = 0; kt < 2; kt++) {
                unsigned bh0 = ksh[s][jrow][kt * 8 + tq];
                unsigned bh1 = ksh[s][jrow][kt * 8 + tq + 4];
                unsigned bl0 = ksl[s][jrow][kt * 8 + tq];
                unsigned bl1 = ksl[s][jrow][kt * 8 + tq + 4];
                const unsigned* ah = &qah[kt * 4];
                const unsigned* al = &qal[kt * 4];
                mma_bf16(c0, c1, c2, c3, ah[0], ah[1], ah[2], ah[3], bh0, bh1);
                mma_bf16(c0, c1, c2, c3, ah[0], ah[1], ah[2], ah[3], bl0, bl1);
                mma_bf16(c0, c1, c2, c3, al[0], al[1], al[2], al[3], bh0, bh1);
            }
            float p0 = ex2(c0 - 4.f), p1 = ex2(c1 - 4.f);
            float p2 = ex2(c2 - 4.f), p3 = ex2(c3 - 4.f);
            lsum[0] += p0 + p1;
            lsum[1] += p2 + p3;
            phi[nb * 2 + 0] = pk_f16x2(p0, p1);   // row g
            phi[nb * 2 + 1] = pk_f16x2(p2, p3);   // row g+8
        }

        // ---- Phase 2: GEMM2 burst (fp16): O += P · V^T ----
#pragma unroll
        for (int kt2 = 0; kt2 < 4; kt2++) {
            const unsigned* ah = &phi[kt2 * 4];
#pragma unroll
            for (int nb2 = 0; nb2 < 4; nb2++) {
                unsigned bh0 = vh[s][nb2 * 8 + g][kt2 * 8 + tq];
                unsigned bh1 = vh[s][nb2 * 8 + g][kt2 * 8 + tq + 4];
                float* o = &oacc[nb2 * 4];
                mma_f16(o[0], o[1], o[2], o[3], ah[0], ah[1], ah[2], ah[3], bh0, bh1);
            }
        }
    }

#pragma unroll
    for (int i = 0; i < 2; i++) {
        lsum[i] += __shfl_xor_sync(FULLM, lsum[i], 1);
        lsum[i] += __shfl_xor_sync(FULLM, lsum[i], 2);
    }
    int b = bh >> 2, h = bh & 3;
    size_t cbase = (size_t)b * NC + h * ND;
    float inv0 = 1.f / lsum[0];
    float inv1 = 1.f / lsum[1];
#pragma unroll
    for (int nb2 = 0; nb2 < 4; nb2++) {
        const float* o = &oacc[nb2 * 4];
        int d0 = nb2 * 8 + 2 * tq;
        out[(cbase + d0    ) * NN + rg    ] = o[0] * inv0;
        out[(cbase + d0 + 1) * NN + rg    ] = o[1] * inv0;
        out[(cbase + d0    ) * NN + rg + 8] = o[2] * inv1;
        out[(cbase + d0 + 1) * NN + rg + 8] = o[3] * inv1;
    }
}

extern "C" void kernel_launch(void* const* d_in, const int* in_sizes, int n_in,
                              void* d_out, int out_size)
{
    const float* x  = (const float*)d_in[0];
    const float* Wq = (const float*)d_in[1];
    const float* rw = (const float*)d_in[2];
    const float* rh = (const float*)d_in[3];
    float* out = (float*)d_out;

    pack_kernel<<<(XTHREADS + WTHREADS + 255) / 256, 256>>>(x, Wq);
    qkv_kernel<<<dim3(8, 3, 16), 256>>>(rw, rh);     // 384 CTAs
    attn_kernel<<<NBH * 8, 256>>>(out);              // 512 CTAs
}